// round 1
// baseline (speedup 1.0000x reference)
#include <cuda_runtime.h>
#include <math.h>

// Problem constants
#define Nn   50000
#define Ee   800000
#define Fdim 128
#define Gn   64
#define OUTC 64
#define EXPN 3
#define TEMP_INV (1.0f/101.0f)

// ---------------- device scratch (no allocations allowed) ----------------
__device__ float g_dinv[Nn];                 // degree -> rsqrt(degree)
__device__ float g_p  [(size_t)Nn * Fdim];   // p = dinv * h   (message payload)
__device__ float g_agg[(size_t)Nn * Fdim];   // aggregated features
__device__ float g_h  [(size_t)Nn * Fdim];   // layer output
__device__ float g_pool[Gn * Fdim];
__device__ float g_cnt [Gn];

// ---------------- degree / norm ----------------
__global__ void k_deg_init() {
    int i = blockIdx.x * blockDim.x + threadIdx.x;
    if (i < Nn) g_dinv[i] = 1.0f;            // self-loop
}
__global__ void k_deg_count(const int* __restrict__ dst) {
    int e = blockIdx.x * blockDim.x + threadIdx.x;
    if (e < Ee) atomicAdd(&g_dinv[dst[e]], 1.0f);
}
__global__ void k_rsqrt() {
    int i = blockIdx.x * blockDim.x + threadIdx.x;
    if (i < Nn) g_dinv[i] = rsqrtf(g_dinv[i]);
}

// ---------------- per-layer prep: p = dinv*h ; agg = p (self-loop term) ----------------
// use_x != 0 -> read from xin (layer 0 input), else read from g_h
__global__ void k_prep(const float4* __restrict__ xin, int use_x) {
    int i = blockIdx.x * blockDim.x + threadIdx.x;   // float4 index
    if (i >= Nn * (Fdim / 4)) return;
    int n = i >> 5;                                   // Fdim/4 = 32 float4 per row
    float4 v = use_x ? xin[i] : ((const float4*)g_h)[i];
    float d = g_dinv[n];
    v.x *= d; v.y *= d; v.z *= d; v.w *= d;
    ((float4*)g_p)[i]   = v;
    ((float4*)g_agg)[i] = v;
}

// ---------------- edge scatter: agg[dst] += p[src]  (one warp per edge) ----------------
__global__ void k_scatter(const int* __restrict__ src, const int* __restrict__ dst) {
    int gid  = blockIdx.x * blockDim.x + threadIdx.x;
    int e    = gid >> 5;
    if (e >= Ee) return;
    int lane = gid & 31;
    int s = src[e];
    int d = dst[e];
    float4 v = ((const float4*)g_p)[s * 32 + lane];
    float* a = g_agg + (size_t)d * Fdim + lane * 4;
    atomicAdd(a + 0, v.x);
    atomicAdd(a + 1, v.y);
    atomicAdd(a + 2, v.z);
    atomicAdd(a + 3, v.w);
}

// ---------------- fused MoE GEMM + gate + relu + combine ----------------
// out[n] = sum_e gate[n][e] * relu( (dinv[n]*agg[n]) @ W[e] + b[e] )
// Block: 64 nodes x 128 cols, 256 threads, 8x4 register tile per thread.
__global__ __launch_bounds__(256, 2)
void k_gemm(const float* __restrict__ W,    // [3,128,128]
            const float* __restrict__ bvec, // [3,128]
            const float* __restrict__ Wg,   // [3,4]
            const float* __restrict__ top)  // [N,4]
{
    __shared__ float sA[64][128];   // dinv*agg tile
    __shared__ float sW[16][128];   // W k-chunk
    __shared__ float sg[64][4];     // gates

    int tid = threadIdx.x;
    int m0  = blockIdx.x * 64;

    // load A tile (dinv-scaled)
    for (int i = tid; i < 64 * 32; i += 256) {
        int m = i >> 5, c = i & 31;
        int n = m0 + m;
        float4 v = make_float4(0.f, 0.f, 0.f, 0.f);
        if (n < Nn) {
            v = ((const float4*)g_agg)[n * 32 + c];
            float d = g_dinv[n];
            v.x *= d; v.y *= d; v.z *= d; v.w *= d;
        }
        ((float4*)&sA[m][0])[c] = v;
    }
    // gates (softmax over 3 experts at temperature)
    if (tid < 64) {
        int n = m0 + tid;
        float l0 = 0.f, l1 = 0.f, l2 = 0.f;
        if (n < Nn) {
            float t0 = top[n*4+0], t1 = top[n*4+1], t2 = top[n*4+2], t3 = top[n*4+3];
            l0 = (t0*Wg[0] + t1*Wg[1] + t2*Wg[2]  + t3*Wg[3])  * TEMP_INV;
            l1 = (t0*Wg[4] + t1*Wg[5] + t2*Wg[6]  + t3*Wg[7])  * TEMP_INV;
            l2 = (t0*Wg[8] + t1*Wg[9] + t2*Wg[10] + t3*Wg[11]) * TEMP_INV;
        }
        float mx = fmaxf(l0, fmaxf(l1, l2));
        float e0 = __expf(l0 - mx), e1 = __expf(l1 - mx), e2 = __expf(l2 - mx);
        float inv = 1.0f / (e0 + e1 + e2);
        sg[tid][0] = e0 * inv; sg[tid][1] = e1 * inv; sg[tid][2] = e2 * inv;
    }

    int tm = tid >> 5;    // 0..7  -> rows  tm*8 .. tm*8+7
    int tn = tid & 31;    // 0..31 -> cols  tn*4 .. tn*4+3

    float o[8][4];
    #pragma unroll
    for (int i = 0; i < 8; i++) { o[i][0]=0.f; o[i][1]=0.f; o[i][2]=0.f; o[i][3]=0.f; }

    for (int e = 0; e < EXPN; e++) {
        float acc[8][4];
        #pragma unroll
        for (int i = 0; i < 8; i++) { acc[i][0]=0.f; acc[i][1]=0.f; acc[i][2]=0.f; acc[i][3]=0.f; }

        const float* We = W + (size_t)e * Fdim * Fdim;
        for (int kc = 0; kc < Fdim; kc += 16) {
            __syncthreads();   // protect previous sW readers (also covers sA/sg first time)
            for (int i = tid; i < 16 * 32; i += 256) {
                int kk = i >> 5, c = i & 31;
                ((float4*)&sW[kk][0])[c] = ((const float4*)(We + (size_t)(kc + kk) * Fdim))[c];
            }
            __syncthreads();
            #pragma unroll
            for (int kk = 0; kk < 16; kk += 4) {
                float4 w0 = ((float4*)&sW[kk + 0][0])[tn];
                float4 w1 = ((float4*)&sW[kk + 1][0])[tn];
                float4 w2 = ((float4*)&sW[kk + 2][0])[tn];
                float4 w3 = ((float4*)&sW[kk + 3][0])[tn];
                #pragma unroll
                for (int i = 0; i < 8; i++) {
                    float4 a = *(const float4*)&sA[tm * 8 + i][kc + kk];
                    acc[i][0] += a.x*w0.x + a.y*w1.x + a.z*w2.x + a.w*w3.x;
                    acc[i][1] += a.x*w0.y + a.y*w1.y + a.z*w2.y + a.w*w3.y;
                    acc[i][2] += a.x*w0.z + a.y*w1.z + a.z*w2.z + a.w*w3.z;
                    acc[i][3] += a.x*w0.w + a.y*w1.w + a.z*w2.w + a.w*w3.w;
                }
            }
        }
        float b0 = bvec[e*Fdim + tn*4 + 0];
        float b1 = bvec[e*Fdim + tn*4 + 1];
        float b2 = bvec[e*Fdim + tn*4 + 2];
        float b3 = bvec[e*Fdim + tn*4 + 3];
        #pragma unroll
        for (int i = 0; i < 8; i++) {
            float g = sg[tm * 8 + i][e];
            o[i][0] += g * fmaxf(acc[i][0] + b0, 0.f);
            o[i][1] += g * fmaxf(acc[i][1] + b1, 0.f);
            o[i][2] += g * fmaxf(acc[i][2] + b2, 0.f);
            o[i][3] += g * fmaxf(acc[i][3] + b3, 0.f);
        }
    }
    #pragma unroll
    for (int i = 0; i < 8; i++) {
        int n = m0 + tm * 8 + i;
        if (n < Nn)
            ((float4*)(g_h + (size_t)n * Fdim))[tn] = make_float4(o[i][0], o[i][1], o[i][2], o[i][3]);
    }
}

// ---------------- pooling ----------------
__global__ void k_pool_zero() {
    int i = blockIdx.x * blockDim.x + threadIdx.x;
    if (i < Gn * Fdim) g_pool[i] = 0.f;
    if (i < Gn)        g_cnt[i]  = 0.f;
}
__global__ void k_pool_acc(const int* __restrict__ batch) {
    int i = blockIdx.x * blockDim.x + threadIdx.x;
    if (i >= Nn * 32) return;
    int n = i >> 5, c = i & 31;
    int g = batch[n];
    float4 v = ((const float4*)g_h)[i];
    float* p = g_pool + g * Fdim + c * 4;
    atomicAdd(p + 0, v.x);
    atomicAdd(p + 1, v.y);
    atomicAdd(p + 2, v.z);
    atomicAdd(p + 3, v.w);
    if (c == 0) atomicAdd(&g_cnt[g], 1.0f);
}
__global__ void k_final(const float* __restrict__ Wf, const float* __restrict__ bf,
                        float* __restrict__ out) {
    __shared__ float sp[Fdim];
    int g = blockIdx.x;
    int j = threadIdx.x;   // 64 threads = OUT cols
    float inv = 1.0f / fmaxf(g_cnt[g], 1.0f);
    for (int i = j; i < Fdim; i += OUTC) sp[i] = g_pool[g * Fdim + i] * inv;
    __syncthreads();
    float acc = bf[j];
    for (int k = 0; k < Fdim; k++) acc += sp[k] * Wf[k * OUTC + j];
    out[g * OUTC + j] = acc;
}

// ---------------- launch ----------------
extern "C" void kernel_launch(void* const* d_in, const int* in_sizes, int n_in,
                              void* d_out, int out_size) {
    const float* x    = (const float*)d_in[0];
    const float* top  = (const float*)d_in[1];
    const int*   ei   = (const int*)  d_in[2];   // [2,E] int32 (jax canonicalizes int64->int32)
    const int*   batch= (const int*)  d_in[3];
    const float* W0   = (const float*)d_in[4];
    const float* b0   = (const float*)d_in[5];
    const float* Wg0  = (const float*)d_in[6];
    const float* W1   = (const float*)d_in[7];
    const float* b1   = (const float*)d_in[8];
    const float* Wg1  = (const float*)d_in[9];
    const float* Wf   = (const float*)d_in[10];
    const float* bf   = (const float*)d_in[11];
    float* out = (float*)d_out;

    const int* src = ei;
    const int* dst = ei + Ee;

    // degree / normalization
    k_deg_init <<<(Nn + 255) / 256, 256>>>();
    k_deg_count<<<(Ee + 255) / 256, 256>>>(dst);
    k_rsqrt    <<<(Nn + 255) / 256, 256>>>();

    int prep_grid = (Nn * 32 + 255) / 256;
    int scat_grid = (int)(((long long)Ee * 32 + 255) / 256);
    int gemm_grid = (Nn + 63) / 64;

    // layer 0 (input = x)
    k_prep   <<<prep_grid, 256>>>((const float4*)x, 1);
    k_scatter<<<scat_grid, 256>>>(src, dst);
    k_gemm   <<<gemm_grid, 256>>>(W0, b0, Wg0, top);

    // layer 1 (input = g_h)
    k_prep   <<<prep_grid, 256>>>((const float4*)x, 0);
    k_scatter<<<scat_grid, 256>>>(src, dst);
    k_gemm   <<<gemm_grid, 256>>>(W1, b1, Wg1, top);

    // global mean pool + final linear
    k_pool_zero<<<(Gn * Fdim + 255) / 256, 256>>>();
    k_pool_acc <<<prep_grid, 256>>>(batch);
    k_final    <<<Gn, OUTC>>>(Wf, bf, out);
}

// round 2
// speedup vs baseline: 2.0622x; 2.0622x over previous
#include <cuda_runtime.h>
#include <math.h>

// Problem constants
#define Nn   50000
#define Ee   800000
#define Fdim 128
#define Gn   64
#define OUTC 64
#define EXPN 3
#define TEMP_INV (1.0f/101.0f)

#define SCAN_B 1024
#define NBLK   ((Nn + SCAN_B - 1) / SCAN_B)   // 49

// ---------------- device scratch ----------------
__device__ float g_dinv[Nn];
__device__ int   g_degi[Nn];
__device__ int   g_off [Nn + 1];
__device__ int   g_cur [Nn];
__device__ int   g_bsum[NBLK];
__device__ int   g_csr [Ee];                  // src ids grouped by dst
__device__ float g_p  [(size_t)Nn * Fdim];    // p = dinv * h
__device__ float g_agg[(size_t)Nn * Fdim];
__device__ float g_h  [(size_t)Nn * Fdim];
__device__ float g_pool[Gn * Fdim];
__device__ float g_cnt [Gn];

// ---------------- degree / CSR build ----------------
__global__ void k_zero_deg() {
    int i = blockIdx.x * blockDim.x + threadIdx.x;
    if (i < Nn) g_degi[i] = 0;
    if (i < Gn * Fdim) g_pool[i] = 0.f;
    if (i < Gn) g_cnt[i] = 0.f;
}
__global__ void k_count(const int* __restrict__ dst) {
    int e = blockIdx.x * blockDim.x + threadIdx.x;
    if (e < Ee) atomicAdd(&g_degi[dst[e]], 1);
}
__global__ void k_rsqrt() {
    int i = blockIdx.x * blockDim.x + threadIdx.x;
    if (i < Nn) g_dinv[i] = rsqrtf((float)(g_degi[i] + 1));  // +1 self loop
}
// block-level exclusive scan of degrees
__global__ void k_scan1() {
    __shared__ int s[SCAN_B];
    int b = blockIdx.x, t = threadIdx.x;
    int i = b * SCAN_B + t;
    int v = (i < Nn) ? g_degi[i] : 0;
    s[t] = v;
    __syncthreads();
    // Hillis-Steele inclusive scan
    for (int d = 1; d < SCAN_B; d <<= 1) {
        int add = (t >= d) ? s[t - d] : 0;
        __syncthreads();
        s[t] += add;
        __syncthreads();
    }
    if (i < Nn) g_off[i] = s[t] - v;           // exclusive within block
    if (t == SCAN_B - 1) g_bsum[b] = s[t];
}
__global__ void k_scan2() {
    if (threadIdx.x == 0) {
        int run = 0;
        for (int b = 0; b < NBLK; b++) { int v = g_bsum[b]; g_bsum[b] = run; run += v; }
        g_off[Nn] = Ee;
    }
}
__global__ void k_scan3() {
    int i = blockIdx.x * blockDim.x + threadIdx.x;
    if (i < Nn) {
        int o = g_off[i] + g_bsum[i / SCAN_B];
        g_off[i] = o;
        g_cur[i] = o;
    }
}
__global__ void k_fill(const int* __restrict__ src, const int* __restrict__ dst) {
    int e = blockIdx.x * blockDim.x + threadIdx.x;
    if (e < Ee) {
        int pos = atomicAdd(&g_cur[dst[e]], 1);
        g_csr[pos] = src[e];
    }
}

// ---------------- per-layer prep: p = dinv*h ----------------
__global__ void k_prep(const float4* __restrict__ xin, int use_x) {
    int i = blockIdx.x * blockDim.x + threadIdx.x;
    if (i >= Nn * (Fdim / 4)) return;
    int n = i >> 5;
    float4 v = use_x ? xin[i] : ((const float4*)g_h)[i];
    float d = g_dinv[n];
    v.x *= d; v.y *= d; v.z *= d; v.w *= d;
    ((float4*)g_p)[i] = v;
}

// ---------------- gather aggregation: one warp per node, no atomics ----------------
__global__ __launch_bounds__(256)
void k_gather() {
    int gid  = blockIdx.x * blockDim.x + threadIdx.x;
    int n    = gid >> 5;
    if (n >= Nn) return;
    int lane = gid & 31;
    const float4* P = (const float4*)g_p;
    float4 acc = P[(size_t)n * 32 + lane];         // self-loop term
    int e   = g_off[n];
    int end = g_off[n + 1];
    for (; e + 2 <= end; e += 2) {
        int s0 = g_csr[e], s1 = g_csr[e + 1];
        float4 v0 = P[(size_t)s0 * 32 + lane];
        float4 v1 = P[(size_t)s1 * 32 + lane];
        acc.x += v0.x + v1.x; acc.y += v0.y + v1.y;
        acc.z += v0.z + v1.z; acc.w += v0.w + v1.w;
    }
    if (e < end) {
        int s = g_csr[e];
        float4 v = P[(size_t)s * 32 + lane];
        acc.x += v.x; acc.y += v.y; acc.z += v.z; acc.w += v.w;
    }
    ((float4*)g_agg)[(size_t)n * 32 + lane] = acc;
}

// ---------------- fused MoE GEMM + gate + relu + combine ----------------
__global__ __launch_bounds__(256, 2)
void k_gemm(const float* __restrict__ W,    // [3,128,128]
            const float* __restrict__ bvec, // [3,128]
            const float* __restrict__ Wg,   // [3,4]
            const float* __restrict__ top)  // [N,4]
{
    __shared__ float sA[64][128];
    __shared__ float sW[16][128];
    __shared__ float sg[64][4];

    int tid = threadIdx.x;
    int m0  = blockIdx.x * 64;

    for (int i = tid; i < 64 * 32; i += 256) {
        int m = i >> 5, c = i & 31;
        int n = m0 + m;
        float4 v = make_float4(0.f, 0.f, 0.f, 0.f);
        if (n < Nn) {
            v = ((const float4*)g_agg)[(size_t)n * 32 + c];
            float d = g_dinv[n];
            v.x *= d; v.y *= d; v.z *= d; v.w *= d;
        }
        ((float4*)&sA[m][0])[c] = v;
    }
    if (tid < 64) {
        int n = m0 + tid;
        float l0 = 0.f, l1 = 0.f, l2 = 0.f;
        if (n < Nn) {
            float t0 = top[n*4+0], t1 = top[n*4+1], t2 = top[n*4+2], t3 = top[n*4+3];
            l0 = (t0*Wg[0] + t1*Wg[1] + t2*Wg[2]  + t3*Wg[3])  * TEMP_INV;
            l1 = (t0*Wg[4] + t1*Wg[5] + t2*Wg[6]  + t3*Wg[7])  * TEMP_INV;
            l2 = (t0*Wg[8] + t1*Wg[9] + t2*Wg[10] + t3*Wg[11]) * TEMP_INV;
        }
        float mx = fmaxf(l0, fmaxf(l1, l2));
        float e0 = __expf(l0 - mx), e1 = __expf(l1 - mx), e2 = __expf(l2 - mx);
        float inv = 1.0f / (e0 + e1 + e2);
        sg[tid][0] = e0 * inv; sg[tid][1] = e1 * inv; sg[tid][2] = e2 * inv;
    }

    int tm = tid >> 5;
    int tn = tid & 31;

    float o[8][4];
    #pragma unroll
    for (int i = 0; i < 8; i++) { o[i][0]=0.f; o[i][1]=0.f; o[i][2]=0.f; o[i][3]=0.f; }

    for (int e = 0; e < EXPN; e++) {
        float acc[8][4];
        #pragma unroll
        for (int i = 0; i < 8; i++) { acc[i][0]=0.f; acc[i][1]=0.f; acc[i][2]=0.f; acc[i][3]=0.f; }

        const float* We = W + (size_t)e * Fdim * Fdim;
        for (int kc = 0; kc < Fdim; kc += 16) {
            __syncthreads();
            for (int i = tid; i < 16 * 32; i += 256) {
                int kk = i >> 5, c = i & 31;
                ((float4*)&sW[kk][0])[c] = ((const float4*)(We + (size_t)(kc + kk) * Fdim))[c];
            }
            __syncthreads();
            #pragma unroll
            for (int kk = 0; kk < 16; kk += 4) {
                float4 w0 = ((float4*)&sW[kk + 0][0])[tn];
                float4 w1 = ((float4*)&sW[kk + 1][0])[tn];
                float4 w2 = ((float4*)&sW[kk + 2][0])[tn];
                float4 w3 = ((float4*)&sW[kk + 3][0])[tn];
                #pragma unroll
                for (int i = 0; i < 8; i++) {
                    float4 a = *(const float4*)&sA[tm * 8 + i][kc + kk];
                    acc[i][0] += a.x*w0.x + a.y*w1.x + a.z*w2.x + a.w*w3.x;
                    acc[i][1] += a.x*w0.y + a.y*w1.y + a.z*w2.y + a.w*w3.y;
                    acc[i][2] += a.x*w0.z + a.y*w1.z + a.z*w2.z + a.w*w3.z;
                    acc[i][3] += a.x*w0.w + a.y*w1.w + a.z*w2.w + a.w*w3.w;
                }
            }
        }
        float b0 = bvec[e*Fdim + tn*4 + 0];
        float b1 = bvec[e*Fdim + tn*4 + 1];
        float b2 = bvec[e*Fdim + tn*4 + 2];
        float b3 = bvec[e*Fdim + tn*4 + 3];
        #pragma unroll
        for (int i = 0; i < 8; i++) {
            float g = sg[tm * 8 + i][e];
            o[i][0] += g * fmaxf(acc[i][0] + b0, 0.f);
            o[i][1] += g * fmaxf(acc[i][1] + b1, 0.f);
            o[i][2] += g * fmaxf(acc[i][2] + b2, 0.f);
            o[i][3] += g * fmaxf(acc[i][3] + b3, 0.f);
        }
    }
    #pragma unroll
    for (int i = 0; i < 8; i++) {
        int n = m0 + tm * 8 + i;
        if (n < Nn)
            ((float4*)(g_h + (size_t)n * Fdim))[tn] = make_float4(o[i][0], o[i][1], o[i][2], o[i][3]);
    }
}

// ---------------- pooling (segment-aware: batch is sorted) ----------------
// block = 128 threads (one per column), 64 nodes per block; flush on graph change
__global__ __launch_bounds__(128)
void k_pool2(const int* __restrict__ batch) {
    int c  = threadIdx.x;
    int n0 = blockIdx.x * 64;
    int nend = n0 + 64; if (nend > Nn) nend = Nn;
    if (n0 >= Nn) return;
    int   curg = batch[n0];
    float acc  = 0.f;
    float cnt  = 0.f;
    for (int n = n0; n < nend; n++) {
        int g = batch[n];
        if (g != curg) {
            atomicAdd(&g_pool[curg * Fdim + c], acc);
            if (c == 0) atomicAdd(&g_cnt[curg], cnt);
            acc = 0.f; cnt = 0.f; curg = g;
        }
        acc += g_h[(size_t)n * Fdim + c];
        cnt += 1.f;
    }
    atomicAdd(&g_pool[curg * Fdim + c], acc);
    if (c == 0) atomicAdd(&g_cnt[curg], cnt);
}

__global__ void k_final(const float* __restrict__ Wf, const float* __restrict__ bf,
                        float* __restrict__ out) {
    __shared__ float sp[Fdim];
    int g = blockIdx.x;
    int j = threadIdx.x;
    float inv = 1.0f / fmaxf(g_cnt[g], 1.0f);
    for (int i = j; i < Fdim; i += OUTC) sp[i] = g_pool[g * Fdim + i] * inv;
    __syncthreads();
    float acc = bf[j];
    for (int k = 0; k < Fdim; k++) acc += sp[k] * Wf[k * OUTC + j];
    out[g * OUTC + j] = acc;
}

// ---------------- launch ----------------
extern "C" void kernel_launch(void* const* d_in, const int* in_sizes, int n_in,
                              void* d_out, int out_size) {
    const float* x    = (const float*)d_in[0];
    const float* top  = (const float*)d_in[1];
    const int*   ei   = (const int*)  d_in[2];
    const int*   batch= (const int*)  d_in[3];
    const float* W0   = (const float*)d_in[4];
    const float* b0   = (const float*)d_in[5];
    const float* Wg0  = (const float*)d_in[6];
    const float* W1   = (const float*)d_in[7];
    const float* b1   = (const float*)d_in[8];
    const float* Wg1  = (const float*)d_in[9];
    const float* Wf   = (const float*)d_in[10];
    const float* bf   = (const float*)d_in[11];
    float* out = (float*)d_out;

    const int* src = ei;
    const int* dst = ei + Ee;

    // CSR build + normalization
    k_zero_deg<<<(Nn + 255) / 256, 256>>>();
    k_count   <<<(Ee + 255) / 256, 256>>>(dst);
    k_rsqrt   <<<(Nn + 255) / 256, 256>>>();
    k_scan1   <<<NBLK, SCAN_B>>>();
    k_scan2   <<<1, 32>>>();
    k_scan3   <<<(Nn + 255) / 256, 256>>>();
    k_fill    <<<(Ee + 255) / 256, 256>>>(src, dst);

    int prep_grid   = (Nn * 32 + 255) / 256;
    int gather_grid = (Nn * 32 + 255) / 256;
    int gemm_grid   = (Nn + 63) / 64;

    // layer 0
    k_prep  <<<prep_grid, 256>>>((const float4*)x, 1);
    k_gather<<<gather_grid, 256>>>();
    k_gemm  <<<gemm_grid, 256>>>(W0, b0, Wg0, top);

    // layer 1
    k_prep  <<<prep_grid, 256>>>((const float4*)x, 0);
    k_gather<<<gather_grid, 256>>>();
    k_gemm  <<<gemm_grid, 256>>>(W1, b1, Wg1, top);

    // pool + final
    k_pool2 <<<(Nn + 63) / 64, 128>>>(batch);
    k_final <<<Gn, OUTC>>>(Wf, bf, out);
}

// round 4
// speedup vs baseline: 2.7652x; 1.3409x over previous
#include <cuda_runtime.h>
#include <cuda_bf16.h>
#include <cstdint>
#include <math.h>

// Problem constants
#define Nn   50000
#define Ee   800000
#define Fdim 128
#define Gn   64
#define OUTC 64
#define EXPN 3
#define TEMP_INV (1.0f/101.0f)

#define SCAN_B 1024
#define NBLK   ((Nn + SCAN_B - 1) / SCAN_B)

// A-tile smem row stride in bytes (128 bf16 = 256B, padded to 272 for
// conflict-free ldmatrix: 272/4=68 words, 68 mod 32 = 4-bank rotation per row)
#define AROW 272
#define ABYTES (128 * AROW)          // 34816 per kind
#define DYN_SMEM (2 * ABYTES)        // hi + lo

// ---------------- device scratch ----------------
__device__ float g_dinv[Nn];
__device__ int   g_degi[Nn];
__device__ int   g_off [Nn + 1];
__device__ int   g_cur [Nn];
__device__ int   g_bsum[NBLK];
__device__ int   g_csr [Ee];
__device__ float g_p  [(size_t)Nn * Fdim];
__device__ float g_agg[(size_t)Nn * Fdim];
__device__ float g_h  [(size_t)Nn * Fdim];
__device__ float g_pool[Gn * Fdim];
__device__ float g_cnt [Gn];
// packed W fragments: [e(3)][kk(8)][ntg(16)][lane(32)] -> uint2 {b0,b1}
__device__ uint2 g_wph0[12288];
__device__ uint2 g_wpl0[12288];
__device__ uint2 g_wph1[12288];
__device__ uint2 g_wpl1[12288];

// ---------------- helpers ----------------
__device__ __forceinline__ void split2(float a, float b, uint32_t& hi, uint32_t& lo) {
    __nv_bfloat162 h = __floats2bfloat162_rn(a, b);
    float ra = a - __bfloat162float(h.x);
    float rb = b - __bfloat162float(h.y);
    __nv_bfloat162 l = __floats2bfloat162_rn(ra, rb);
    hi = *reinterpret_cast<uint32_t*>(&h);
    lo = *reinterpret_cast<uint32_t*>(&l);
}
__device__ __forceinline__ uint32_t smem_u32(const void* p) {
    uint32_t a;
    asm("{ .reg .u64 t; cvta.to.shared.u64 t, %1; cvt.u32.u64 %0, t; }" : "=r"(a) : "l"(p));
    return a;
}
__device__ __forceinline__ void ldsm4(uint32_t* r, uint32_t addr) {
    asm volatile("ldmatrix.sync.aligned.m8n8.x4.shared.b16 {%0,%1,%2,%3}, [%4];"
        : "=r"(r[0]), "=r"(r[1]), "=r"(r[2]), "=r"(r[3]) : "r"(addr));
}
__device__ __forceinline__ void mma16816(float* d, const uint32_t* a, uint2 b) {
    asm volatile("mma.sync.aligned.m16n8k16.row.col.f32.bf16.bf16.f32 "
        "{%0,%1,%2,%3}, {%4,%5,%6,%7}, {%8,%9}, {%0,%1,%2,%3};"
        : "+f"(d[0]), "+f"(d[1]), "+f"(d[2]), "+f"(d[3])
        : "r"(a[0]), "r"(a[1]), "r"(a[2]), "r"(a[3]), "r"(b.x), "r"(b.y));
}

// ---------------- degree / CSR build ----------------
__global__ void k_zero_deg() {
    int i = blockIdx.x * blockDim.x + threadIdx.x;
    if (i < Nn) g_degi[i] = 0;
    if (i < Gn * Fdim) g_pool[i] = 0.f;
    if (i < Gn) g_cnt[i] = 0.f;
}
__global__ void k_count(const int* __restrict__ dst) {
    int e = blockIdx.x * blockDim.x + threadIdx.x;
    if (e < Ee) atomicAdd(&g_degi[dst[e]], 1);
}
__global__ void k_rsqrt() {
    int i = blockIdx.x * blockDim.x + threadIdx.x;
    if (i < Nn) g_dinv[i] = rsqrtf((float)(g_degi[i] + 1));
}
__global__ void k_scan1() {
    __shared__ int s[SCAN_B];
    int b = blockIdx.x, t = threadIdx.x;
    int i = b * SCAN_B + t;
    int v = (i < Nn) ? g_degi[i] : 0;
    s[t] = v;
    __syncthreads();
    for (int d = 1; d < SCAN_B; d <<= 1) {
        int add = (t >= d) ? s[t - d] : 0;
        __syncthreads();
        s[t] += add;
        __syncthreads();
    }
    if (i < Nn) g_off[i] = s[t] - v;
    if (t == SCAN_B - 1) g_bsum[b] = s[t];
}
__global__ void k_scan2() {
    if (threadIdx.x == 0) {
        int run = 0;
        for (int b = 0; b < NBLK; b++) { int v = g_bsum[b]; g_bsum[b] = run; run += v; }
        g_off[Nn] = Ee;
    }
}
__global__ void k_scan3() {
    int i = blockIdx.x * blockDim.x + threadIdx.x;
    if (i < Nn) {
        int o = g_off[i] + g_bsum[i / SCAN_B];
        g_off[i] = o;
        g_cur[i] = o;
    }
}
__global__ void k_fill(const int* __restrict__ src, const int* __restrict__ dst) {
    int e = blockIdx.x * blockDim.x + threadIdx.x;
    if (e < Ee) {
        int pos = atomicAdd(&g_cur[dst[e]], 1);
        g_csr[pos] = src[e];
    }
}

// ---------------- W fragment packing ----------------
// thread per (e, kk, ntg, lane): b0={W[k0][n],W[k0+1][n]}, b1={W[k0+8][n],W[k0+9][n]}
__global__ void k_wsplit(const float* __restrict__ W, int layer) {
    int idx = blockIdx.x * blockDim.x + threadIdx.x;
    if (idx >= 12288) return;
    int lane = idx & 31;
    int ntg  = (idx >> 5) & 15;
    int kk   = (idx >> 9) & 7;
    int e    = idx >> 12;
    int n  = ntg * 8 + (lane >> 2);
    int k0 = kk * 16 + (lane & 3) * 2;
    const float* We = W + (size_t)e * Fdim * Fdim;
    uint32_t h0, l0, h1, l1;
    split2(We[(size_t)k0 * Fdim + n],       We[(size_t)(k0 + 1) * Fdim + n], h0, l0);
    split2(We[(size_t)(k0 + 8) * Fdim + n], We[(size_t)(k0 + 9) * Fdim + n], h1, l1);
    uint2* ph = layer ? g_wph1 : g_wph0;
    uint2* pl = layer ? g_wpl1 : g_wpl0;
    ph[idx] = make_uint2(h0, h1);
    pl[idx] = make_uint2(l0, l1);
}

// ---------------- per-layer prep: p = dinv*h ----------------
__global__ void k_prep(const float4* __restrict__ xin, int use_x) {
    int i = blockIdx.x * blockDim.x + threadIdx.x;
    if (i >= Nn * (Fdim / 4)) return;
    int n = i >> 5;
    float4 v = use_x ? xin[i] : ((const float4*)g_h)[i];
    float d = g_dinv[n];
    v.x *= d; v.y *= d; v.z *= d; v.w *= d;
    ((float4*)g_p)[i] = v;
}

// ---------------- gather aggregation: one warp per node ----------------
__global__ __launch_bounds__(256)
void k_gather() {
    int gid  = blockIdx.x * blockDim.x + threadIdx.x;
    int n    = gid >> 5;
    if (n >= Nn) return;
    int lane = gid & 31;
    const float4* P = (const float4*)g_p;
    float4 acc = P[(size_t)n * 32 + lane];
    int e   = g_off[n];
    int end = g_off[n + 1];
    for (; e + 2 <= end; e += 2) {
        int s0 = g_csr[e], s1 = g_csr[e + 1];
        float4 v0 = P[(size_t)s0 * 32 + lane];
        float4 v1 = P[(size_t)s1 * 32 + lane];
        acc.x += v0.x + v1.x; acc.y += v0.y + v1.y;
        acc.z += v0.z + v1.z; acc.w += v0.w + v1.w;
    }
    if (e < end) {
        int s = g_csr[e];
        float4 v = P[(size_t)s * 32 + lane];
        acc.x += v.x; acc.y += v.y; acc.z += v.z; acc.w += v.w;
    }
    ((float4*)g_agg)[(size_t)n * 32 + lane] = acc;
}

// ---------------- MoE GEMM via mma.sync bf16 split ----------------
// 512 threads, 128-node x 128-col tile. 16 warps: wm = w&3 (32 rows), wn = w>>2 (32 cols).
extern __shared__ char dynA[];   // [A_hi 34816][A_lo 34816]
__global__ __launch_bounds__(512)
void k_gemm_mma(int layer,
                const float* __restrict__ bvec, // [3,128]
                const float* __restrict__ Wg,   // [3,4]
                const float* __restrict__ top)  // [N,4]
{
    __shared__ float sgate[128][4];

    int tid  = threadIdx.x;
    int m0   = blockIdx.x * 128;

    // ---- gates ----
    if (tid < 128) {
        int n = m0 + tid;
        float l0 = 0.f, l1 = 0.f, l2 = 0.f;
        if (n < Nn) {
            float t0 = top[n*4+0], t1 = top[n*4+1], t2 = top[n*4+2], t3 = top[n*4+3];
            l0 = (t0*Wg[0] + t1*Wg[1] + t2*Wg[2]  + t3*Wg[3])  * TEMP_INV;
            l1 = (t0*Wg[4] + t1*Wg[5] + t2*Wg[6]  + t3*Wg[7])  * TEMP_INV;
            l2 = (t0*Wg[8] + t1*Wg[9] + t2*Wg[10] + t3*Wg[11]) * TEMP_INV;
        }
        float mx = fmaxf(l0, fmaxf(l1, l2));
        float e0 = __expf(l0 - mx), e1 = __expf(l1 - mx), e2 = __expf(l2 - mx);
        float inv = 1.0f / (e0 + e1 + e2);
        sgate[tid][0] = e0 * inv; sgate[tid][1] = e1 * inv; sgate[tid][2] = e2 * inv;
    }

    // ---- A tile: dinv*agg -> bf16 hi/lo in smem (row-major, AROW-byte rows) ----
    for (int idx = tid; idx < 8192; idx += 512) {       // 128 rows x 64 float2
        int row = idx >> 6;
        int kp  = idx & 63;
        int n   = m0 + row;
        float2 v = make_float2(0.f, 0.f);
        float  d = 0.f;
        if (n < Nn) {
            v = ((const float2*)g_agg)[(size_t)n * 64 + kp];
            d = g_dinv[n];
        }
        uint32_t hi, lo;
        split2(v.x * d, v.y * d, hi, lo);
        *reinterpret_cast<uint32_t*>(dynA + row * AROW + kp * 4)          = hi;
        *reinterpret_cast<uint32_t*>(dynA + ABYTES + row * AROW + kp * 4) = lo;
    }
    __syncthreads();

    int w    = tid >> 5;
    int lane = tid & 31;
    int wm   = w & 3;       // 32-row group
    int wn   = w >> 2;      // 32-col group

    uint32_t aBase = smem_u32(dynA);
    // ldmatrix address: row = wm*32 + mt*16 + (lane&15), kbyte = kk*32 + (lane>>4)*16
    uint32_t aAddr0 = aBase + (uint32_t)(wm * 32 + (lane & 15)) * AROW + (uint32_t)(lane >> 4) * 16;

    const uint2* wph = layer ? g_wph1 : g_wph0;
    const uint2* wpl = layer ? g_wpl1 : g_wpl0;

    float out[2][4][4];
    #pragma unroll
    for (int mt = 0; mt < 2; mt++)
        #pragma unroll
        for (int nt = 0; nt < 4; nt++)
            #pragma unroll
            for (int r = 0; r < 4; r++) out[mt][nt][r] = 0.f;

    int r0 = wm * 32 + (lane >> 2);     // D-fragment row (mt adds 16, +8 for d2/d3)

    for (int e = 0; e < EXPN; e++) {
        float acc[2][4][4];
        #pragma unroll
        for (int mt = 0; mt < 2; mt++)
            #pragma unroll
            for (int nt = 0; nt < 4; nt++)
                #pragma unroll
                for (int r = 0; r < 4; r++) acc[mt][nt][r] = 0.f;

        #pragma unroll
        for (int p = 0; p < 3; p++) {
            const uint2* Bp = ((p == 1) ? wpl : wph) + e * 4096 + (wn * 4) * 32 + lane;
            uint32_t aOff = aAddr0 + ((p == 2) ? ABYTES : 0u);
            #pragma unroll
            for (int kk = 0; kk < 8; kk++) {
                uint32_t a0[4], a1[4];
                ldsm4(a0, aOff + kk * 32);
                ldsm4(a1, aOff + kk * 32 + 16 * AROW);
                const uint2* Bk = Bp + kk * 512;
                #pragma unroll
                for (int nt = 0; nt < 4; nt++) {
                    uint2 b = Bk[nt * 32];
                    mma16816(acc[0][nt], a0, b);
                    mma16816(acc[1][nt], a1, b);
                }
            }
        }
        // epilogue: out += gate * relu(acc + bias)
        #pragma unroll
        for (int mt = 0; mt < 2; mt++) {
            float gA = sgate[r0 + mt * 16][e];
            float gB = sgate[r0 + mt * 16 + 8][e];
            #pragma unroll
            for (int nt = 0; nt < 4; nt++) {
                float2 bias = *(const float2*)(bvec + e * Fdim + wn * 32 + nt * 8 + (lane & 3) * 2);
                out[mt][nt][0] += gA * fmaxf(acc[mt][nt][0] + bias.x, 0.f);
                out[mt][nt][1] += gA * fmaxf(acc[mt][nt][1] + bias.y, 0.f);
                out[mt][nt][2] += gB * fmaxf(acc[mt][nt][2] + bias.x, 0.f);
                out[mt][nt][3] += gB * fmaxf(acc[mt][nt][3] + bias.y, 0.f);
            }
        }
    }

    // ---- store ----
    #pragma unroll
    for (int mt = 0; mt < 2; mt++) {
        int ra = m0 + r0 + mt * 16;
        int rb = ra + 8;
        #pragma unroll
        for (int nt = 0; nt < 4; nt++) {
            int col = wn * 32 + nt * 8 + (lane & 3) * 2;
            if (ra < Nn)
                *(float2*)(g_h + (size_t)ra * Fdim + col) = make_float2(out[mt][nt][0], out[mt][nt][1]);
            if (rb < Nn)
                *(float2*)(g_h + (size_t)rb * Fdim + col) = make_float2(out[mt][nt][2], out[mt][nt][3]);
        }
    }
}

// ---------------- pooling (segment-aware: batch is sorted) ----------------
__global__ __launch_bounds__(128)
void k_pool2(const int* __restrict__ batch) {
    int c  = threadIdx.x;
    int n0 = blockIdx.x * 64;
    int nend = n0 + 64; if (nend > Nn) nend = Nn;
    if (n0 >= Nn) return;
    int   curg = batch[n0];
    float acc  = 0.f;
    float cnt  = 0.f;
    for (int n = n0; n < nend; n++) {
        int g = batch[n];
        if (g != curg) {
            atomicAdd(&g_pool[curg * Fdim + c], acc);
            if (c == 0) atomicAdd(&g_cnt[curg], cnt);
            acc = 0.f; cnt = 0.f; curg = g;
        }
        acc += g_h[(size_t)n * Fdim + c];
        cnt += 1.f;
    }
    atomicAdd(&g_pool[curg * Fdim + c], acc);
    if (c == 0) atomicAdd(&g_cnt[curg], cnt);
}

__global__ void k_final(const float* __restrict__ Wf, const float* __restrict__ bf,
                        float* __restrict__ out) {
    __shared__ float sp[Fdim];
    int g = blockIdx.x;
    int j = threadIdx.x;
    float inv = 1.0f / fmaxf(g_cnt[g], 1.0f);
    for (int i = j; i < Fdim; i += OUTC) sp[i] = g_pool[g * Fdim + i] * inv;
    __syncthreads();
    float acc = bf[j];
    for (int k = 0; k < Fdim; k++) acc += sp[k] * Wf[k * OUTC + j];
    out[g * OUTC + j] = acc;
}

// ---------------- launch ----------------
extern "C" void kernel_launch(void* const* d_in, const int* in_sizes, int n_in,
                              void* d_out, int out_size) {
    const float* x    = (const float*)d_in[0];
    const float* top  = (const float*)d_in[1];
    const int*   ei   = (const int*)  d_in[2];
    const int*   batch= (const int*)  d_in[3];
    const float* W0   = (const float*)d_in[4];
    const float* b0   = (const float*)d_in[5];
    const float* Wg0  = (const float*)d_in[6];
    const float* W1   = (const float*)d_in[7];
    const float* b1   = (const float*)d_in[8];
    const float* Wg1  = (const float*)d_in[9];
    const float* Wf   = (const float*)d_in[10];
    const float* bf   = (const float*)d_in[11];
    float* out = (float*)d_out;

    const int* src = ei;
    const int* dst = ei + Ee;

    cudaFuncSetAttribute(k_gemm_mma, cudaFuncAttributeMaxDynamicSharedMemorySize, DYN_SMEM);

    // CSR build + normalization + W packing
    k_zero_deg<<<(Nn + 255) / 256, 256>>>();
    k_count   <<<(Ee + 255) / 256, 256>>>(dst);
    k_rsqrt   <<<(Nn + 255) / 256, 256>>>();
    k_scan1   <<<NBLK, SCAN_B>>>();
    k_scan2   <<<1, 32>>>();
    k_scan3   <<<(Nn + 255) / 256, 256>>>();
    k_fill    <<<(Ee + 255) / 256, 256>>>(src, dst);
    k_wsplit  <<<48, 256>>>(W0, 0);
    k_wsplit  <<<48, 256>>>(W1, 1);

    int prep_grid = (Nn * 32 + 255) / 256;
    int gemm_grid = (Nn + 127) / 128;

    // layer 0
    k_prep    <<<prep_grid, 256>>>((const float4*)x, 1);
    k_gather  <<<prep_grid, 256>>>();
    k_gemm_mma<<<gemm_grid, 512, DYN_SMEM>>>(0, b0, Wg0, top);

    // layer 1
    k_prep    <<<prep_grid, 256>>>((const float4*)x, 0);
    k_gather  <<<prep_grid, 256>>>();
    k_gemm_mma<<<gemm_grid, 512, DYN_SMEM>>>(1, b1, Wg1, top);

    // pool + final
    k_pool2 <<<(Nn + 63) / 64, 128>>>(batch);
    k_final <<<Gn, OUTC>>>(Wf, bf, out);
}